// round 13
// baseline (speedup 1.0000x reference)
#include <cuda_runtime.h>
#include <math.h>

// Fixed-shape problem: B=128, S=512, L=64
#define BB 128
#define SB 512
#define LL 64
#define LDE 68                // padded smem row stride (floats), 16B-aligned rows
#define GRID_MAIN 512         // blocks; each does 2 tiles of 64 pairs (1024 tiles)

__device__ float g_alpha_part[GRID_MAIN * LL];
__device__ float g_sc4[GRID_MAIN];     // per-(batch,quarter) score partial
__device__ int   g_cnt4[GRID_MAIN];    // per-(batch,quarter) mask count

// ---- packed f32x2 helpers (Blackwell FFMA2) ----
__device__ __forceinline__ unsigned long long pk2(float lo, float hi) {
    unsigned long long r;
    asm("mov.b64 %0, {%1,%2};" : "=l"(r) : "f"(lo), "f"(hi));
    return r;
}
__device__ __forceinline__ void fma2(unsigned long long &d, unsigned long long a, unsigned long long b) {
    asm("fma.rn.f32x2 %0, %1, %2, %0;" : "+l"(d) : "l"(a), "l"(b));
}
__device__ __forceinline__ float2 up2(unsigned long long v) {
    float2 r;
    asm("mov.b64 {%0,%1}, %2;" : "=f"(r.x), "=f"(r.y) : "l"(v));
    return r;
}

// ============================================================================
// Kernel A (unchanged — measured ~21us in R11): per pair p=(b,s):
//   v_i = sum_j exp(T[i,j]) * exp(emit[p,j]); acc += w_p * log(v_i),
//   w_p = (b != 0) && mask[p].   (2 LDS.128 + 8 MOV + 8 FFMA2 per k)
// Phase 2 (appended, cheap): score partial for quarter q of batch b (g=4b+q).
// NO fences, NO atomics — kernel boundary publishes results.
// ============================================================================
__global__ void __launch_bounds__(256, 4)
k_A(const float* __restrict__ emit,
    const int*   __restrict__ labels,
    const int*   __restrict__ mask,
    const float* __restrict__ trans) {
    __shared__ __align__(16) float sT[64 * LDE];   // sT[k*LDE + i] = exp(T[i][k])
    __shared__ __align__(16) float sE[64 * LDE];   // sE[k*LDE + m] = exp(emit[pair m][k])
    __shared__ __align__(16) float sRed[64 * 17];  // epilogue partials

    const int tid = threadIdx.x;

    // Load + exp + transpose T (once per block).
#pragma unroll
    for (int r = 0; r < 16; r++) {
        int idx = tid + 256 * r;                    // idx = i*64 + k
        sT[(idx & 63) * LDE + (idx >> 6)] = __expf(trans[idx]);
    }

    const int tx = tid & 15;          // output-column group (4 i's)
    const int ty = tid >> 4;          // pair-row group (4 m's)
    const int lm = tid >> 2;          // load: row m (0..63), 4 threads per row
    const int lk = (tid & 3) * 16;    // load: k-base

    float accA = 0.0f;                // meaningful for tid < 64

    for (int it = 0; it < 2; it++) {
        const int pbase = (blockIdx.x * 2 + it) * 64;

        // Load 16 contiguous floats of row (pbase+lm), k = lk..lk+15
        const float4* src = reinterpret_cast<const float4*>(emit + (pbase + lm) * LL + lk);
        float4 f0 = src[0], f1 = src[1], f2 = src[2], f3 = src[3];
        float ev[16] = {f0.x, f0.y, f0.z, f0.w, f1.x, f1.y, f1.z, f1.w,
                        f2.x, f2.y, f2.z, f2.w, f3.x, f3.y, f3.z, f3.w};

        const int p0 = pbase + 4 * ty;  // this thread's 4 pair rows (mask is int32)
        float w0 = ((p0 + 0) >= SB && mask[p0 + 0] != 0) ? 1.0f : 0.0f;
        float w1 = ((p0 + 1) >= SB && mask[p0 + 1] != 0) ? 1.0f : 0.0f;
        float w2 = ((p0 + 2) >= SB && mask[p0 + 2] != 0) ? 1.0f : 0.0f;
        float w3 = ((p0 + 3) >= SB && mask[p0 + 3] != 0) ? 1.0f : 0.0f;

#pragma unroll
        for (int u = 0; u < 16; u++)
            sE[(lk + u) * LDE + lm] = __expf(ev[u]);
        __syncthreads();   // sE (and first-iter sT) ready

        // 4x4 register tile: acc[mpair][i], packed m-pairs.
        unsigned long long a00 = 0ull, a01 = 0ull, a02 = 0ull, a03 = 0ull;
        unsigned long long a10 = 0ull, a11 = 0ull, a12 = 0ull, a13 = 0ull;
        const float* pT = sT + 4 * tx;
        const float* pE = sE + 4 * ty;
#pragma unroll 8
        for (int k = 0; k < 64; k++) {
            float4 tf = *reinterpret_cast<const float4*>(pT + k * LDE);
            ulonglong2 ef = *reinterpret_cast<const ulonglong2*>(pE + k * LDE);
            unsigned long long t0 = pk2(tf.x, tf.x);
            unsigned long long t1 = pk2(tf.y, tf.y);
            unsigned long long t2 = pk2(tf.z, tf.z);
            unsigned long long t3 = pk2(tf.w, tf.w);
            fma2(a00, ef.x, t0); fma2(a10, ef.y, t0);
            fma2(a01, ef.x, t1); fma2(a11, ef.y, t1);
            fma2(a02, ef.x, t2); fma2(a12, ef.y, t2);
            fma2(a03, ef.x, t3); fma2(a13, ef.y, t3);
        }

        // Epilogue: log, mask-weight, reduce over pairs.
        float2 u0, u1;
        u0 = up2(a00); u1 = up2(a10);
        float r0 = w0 * __logf(u0.x) + w1 * __logf(u0.y) + w2 * __logf(u1.x) + w3 * __logf(u1.y);
        u0 = up2(a01); u1 = up2(a11);
        float r1 = w0 * __logf(u0.x) + w1 * __logf(u0.y) + w2 * __logf(u1.x) + w3 * __logf(u1.y);
        u0 = up2(a02); u1 = up2(a12);
        float r2 = w0 * __logf(u0.x) + w1 * __logf(u0.y) + w2 * __logf(u1.x) + w3 * __logf(u1.y);
        u0 = up2(a03); u1 = up2(a13);
        float r3 = w0 * __logf(u0.x) + w1 * __logf(u0.y) + w2 * __logf(u1.x) + w3 * __logf(u1.y);

        sRed[(4 * tx + 0) * 17 + ty] = r0;
        sRed[(4 * tx + 1) * 17 + ty] = r1;
        sRed[(4 * tx + 2) * 17 + ty] = r2;
        sRed[(4 * tx + 3) * 17 + ty] = r3;
        __syncthreads();   // sRed ready; also all sE reads of this tile done

        if (tid < 64) {
            float s = 0.0f;
#pragma unroll
            for (int y2 = 0; y2 < 16; y2++) s += sRed[tid * 17 + y2];
            accA += s;
        }
        // Safe: next sRed writes happen only after the next sE-fill barrier.
    }

    if (tid < 64) g_alpha_part[blockIdx.x * LL + tid] = accA;
    __syncthreads();   // sRed reads done before phase-2 reuse

    // ---- Phase 2: score partial for (batch b, quarter q), g = blockIdx ----
    {
        const int g = blockIdx.x;
        const int b = g >> 2, q = g & 3;
        float acc = 0.0f; int cnt = 0;
        if (tid < 128) {
            const int s = q * 128 + tid;
            int lab = labels[b * SB + s];
            int mm  = mask[b * SB + s];
            if (mm != 0) {
                float v = emit[(b * SB + s) * LL + lab];
                if (s > 0) v += trans[labels[b * SB + s - 1] * LL + lab];
                acc = v; cnt = 1;
            }
        }
        float* rA = sRed;                       // 128 floats
        int*   rC = (int*)(sRed + 128);         // 128 ints
        if (tid < 128) { rA[tid] = acc; rC[tid] = cnt; }
        __syncthreads();
#pragma unroll
        for (int o = 64; o > 0; o >>= 1) {
            if (tid < o) { rA[tid] += rA[tid + o]; rC[tid] += rC[tid + o]; }
            __syncthreads();
        }
        if (tid == 0) { g_sc4[g] = rA[0]; g_cnt4[g] = rC[0]; }
    }
}

// ============================================================================
// Kernel B: single block, 512 threads — deterministic fp64 combine.
// MLP fix: each thread sums its 64 block-partials into 8 INDEPENDENT
// accumulators (8 loads in flight per batch), then a fixed-order combine.
// ============================================================================
__global__ void __launch_bounds__(512)
k_B(const float* __restrict__ emit,
    const int*   __restrict__ labels,
    const float* __restrict__ strans,
    const float* __restrict__ etrans,
    float* __restrict__ out) {
    __shared__ double sP[8 * 64];
    __shared__ double sM[64];
    __shared__ double sSc[128];

    const int tid = threadIdx.x;
    const int i  = tid & 63;     // alpha lane
    const int q8 = tid >> 6;     // eighth 0..7 (64 blocks each)

    {
        const float* ap = g_alpha_part + q8 * 64 * LL + i;
        double acc[8];
#pragma unroll
        for (int u = 0; u < 8; u++) acc[u] = 0.0;
#pragma unroll
        for (int j = 0; j < 8; j++) {
            // 8 independent loads per batch — MLP=8, chains split 8 ways.
            float v0 = ap[(j * 8 + 0) * LL];
            float v1 = ap[(j * 8 + 1) * LL];
            float v2 = ap[(j * 8 + 2) * LL];
            float v3 = ap[(j * 8 + 3) * LL];
            float v4 = ap[(j * 8 + 4) * LL];
            float v5 = ap[(j * 8 + 5) * LL];
            float v6 = ap[(j * 8 + 6) * LL];
            float v7 = ap[(j * 8 + 7) * LL];
            acc[0] += (double)v0; acc[1] += (double)v1;
            acc[2] += (double)v2; acc[3] += (double)v3;
            acc[4] += (double)v4; acc[5] += (double)v5;
            acc[6] += (double)v6; acc[7] += (double)v7;
        }
        sP[q8 * 64 + i] = ((acc[0] + acc[1]) + (acc[2] + acc[3]))
                        + ((acc[4] + acc[5]) + (acc[6] + acc[7]));
    }
    __syncthreads();

    double a = 0.0;
    if (tid < 64) {
        a = (double)emit[i]
          + (((sP[i]       + sP[64 + i])  + (sP[128 + i] + sP[192 + i]))
           + ((sP[256 + i] + sP[320 + i]) + (sP[384 + i] + sP[448 + i])));
        sM[i] = a;
    }
    __syncthreads();
#pragma unroll
    for (int o = 32; o > 0; o >>= 1) {
        if (tid < o) sM[tid] = fmax(sM[tid], sM[tid + o]);
        __syncthreads();
    }
    const double mx = sM[0];
    __syncthreads();
    if (tid < 64) sM[i] = exp(a - mx);
    __syncthreads();
#pragma unroll
    for (int o = 32; o > 0; o >>= 1) {
        if (tid < o) sM[tid] += sM[tid + o];
        __syncthreads();
    }
    const double sumE = sM[0];

    if (tid < 128) {
        const int b = tid;
        // 4 independent loads each for cnt/sc (MLP), then fixed combine.
        int c0 = g_cnt4[4 * b], c1 = g_cnt4[4 * b + 1];
        int c2 = g_cnt4[4 * b + 2], c3 = g_cnt4[4 * b + 3];
        float s0 = g_sc4[4 * b], s1 = g_sc4[4 * b + 1];
        float s2 = g_sc4[4 * b + 2], s3 = g_sc4[4 * b + 3];
        int cnt = (c0 + c1) + (c2 + c3);
        double sc = ((double)s0 + (double)s1) + ((double)s2 + (double)s3);
        sc += (double)strans[labels[b * SB]] + (double)etrans[labels[b * SB + cnt - 1]];
        sSc[b] = sc;
    }
    __syncthreads();
#pragma unroll
    for (int o = 64; o > 0; o >>= 1) {
        if (tid < o) sSc[tid] += sSc[tid + o];
        __syncthreads();
    }

    if (tid == 0) {
        double logZ = mx + log(sumE);
        out[0] = (float)((logZ - sSc[0]) / (double)BB);
    }
}

// ============================================================================
// kernel_launch — two kernels (stream-ordered; graph-capturable).
// Inputs: emit f32[B,S,L], labels i32[B,S], mask i32[B,S] (bool as int32),
//         transitions f32[L,L], strans f32[L], etrans f32[L]. Output f32[1].
// ============================================================================
extern "C" void kernel_launch(void* const* d_in, const int* in_sizes, int n_in,
                              void* d_out, int out_size) {
    const float* emit   = (const float*)d_in[0];
    const int*   labels = (const int*)d_in[1];
    const int*   mask   = (const int*)d_in[2];
    const float* trans  = (const float*)d_in[3];
    const float* strans = (const float*)d_in[4];
    const float* etrans = (const float*)d_in[5];
    float* out = (float*)d_out;

    k_A<<<GRID_MAIN, 256>>>(emit, labels, mask, trans);
    k_B<<<1, 512>>>(emit, labels, strans, etrans, out);
}

// round 15
// speedup vs baseline: 1.3323x; 1.3323x over previous
#include <cuda_runtime.h>
#include <math.h>

// Fixed-shape problem: B=128, S=512, L=64
#define BB 128
#define SB 512
#define LL 64
#define LDE 68                // padded smem row stride (floats), 16B-aligned rows
#define GRID_MAIN 512         // blocks; each does 2 tiles of 64 pairs (1024 tiles)

__device__ float g_alpha[LL];      // atomic alpha accumulator (reset by k_B)
__device__ float g_score;          // atomic score accumulator (reset by k_B)
__device__ int   g_cntB[BB];       // per-batch mask count (atomic int, reset by k_B)

// ---- packed f32x2 helpers (Blackwell FFMA2) ----
__device__ __forceinline__ unsigned long long pk2(float lo, float hi) {
    unsigned long long r;
    asm("mov.b64 %0, {%1,%2};" : "=l"(r) : "f"(lo), "f"(hi));
    return r;
}
__device__ __forceinline__ void fma2(unsigned long long &d, unsigned long long a, unsigned long long b) {
    asm("fma.rn.f32x2 %0, %1, %2, %0;" : "+l"(d) : "l"(a), "l"(b));
}
__device__ __forceinline__ float2 up2(unsigned long long v) {
    float2 r;
    asm("mov.b64 {%0,%1}, %2;" : "=f"(r.x), "=f"(r.y) : "l"(v));
    return r;
}

// ============================================================================
// Kernel A: phase 1 = measured ~21us GEMM: per pair p=(b,s):
//   v_i = sum_j exp(T[i,j]) * exp(emit[p,j]); acc += w_p * log(v_i),
//   w_p = (b != 0) && mask[p].
// Results are ATOMICALLY accumulated into tiny global slots so kernel B has
// no bulk reduction left to do.
// Phase 2: score partial for quarter q of batch b (g = 4b+q) -> atomics.
// ============================================================================
__global__ void __launch_bounds__(256, 4)
k_A(const float* __restrict__ emit,
    const int*   __restrict__ labels,
    const int*   __restrict__ mask,
    const float* __restrict__ trans,
    const float* __restrict__ strans) {
    __shared__ __align__(16) float sT[64 * LDE];   // sT[k*LDE + i] = exp(T[i][k])
    __shared__ __align__(16) float sE[64 * LDE];   // sE[k*LDE + m] = exp(emit[pair m][k])
    __shared__ __align__(16) float sRed[64 * 17];  // epilogue partials

    const int tid = threadIdx.x;

    // Load + exp + transpose T (once per block).
#pragma unroll
    for (int r = 0; r < 16; r++) {
        int idx = tid + 256 * r;                    // idx = i*64 + k
        sT[(idx & 63) * LDE + (idx >> 6)] = __expf(trans[idx]);
    }

    const int tx = tid & 15;          // output-column group (4 i's)
    const int ty = tid >> 4;          // pair-row group (4 m's)
    const int lm = tid >> 2;          // load: row m (0..63), 4 threads per row
    const int lk = (tid & 3) * 16;    // load: k-base

    float accA = 0.0f;                // meaningful for tid < 64

    for (int it = 0; it < 2; it++) {
        const int pbase = (blockIdx.x * 2 + it) * 64;

        // Load 16 contiguous floats of row (pbase+lm), k = lk..lk+15
        const float4* src = reinterpret_cast<const float4*>(emit + (pbase + lm) * LL + lk);
        float4 f0 = src[0], f1 = src[1], f2 = src[2], f3 = src[3];
        float ev[16] = {f0.x, f0.y, f0.z, f0.w, f1.x, f1.y, f1.z, f1.w,
                        f2.x, f2.y, f2.z, f2.w, f3.x, f3.y, f3.z, f3.w};

        const int p0 = pbase + 4 * ty;  // this thread's 4 pair rows (mask is int32)
        float w0 = ((p0 + 0) >= SB && mask[p0 + 0] != 0) ? 1.0f : 0.0f;
        float w1 = ((p0 + 1) >= SB && mask[p0 + 1] != 0) ? 1.0f : 0.0f;
        float w2 = ((p0 + 2) >= SB && mask[p0 + 2] != 0) ? 1.0f : 0.0f;
        float w3 = ((p0 + 3) >= SB && mask[p0 + 3] != 0) ? 1.0f : 0.0f;

#pragma unroll
        for (int u = 0; u < 16; u++)
            sE[(lk + u) * LDE + lm] = __expf(ev[u]);
        __syncthreads();   // sE (and first-iter sT) ready

        // 4x4 register tile: acc[mpair][i], packed m-pairs.
        unsigned long long a00 = 0ull, a01 = 0ull, a02 = 0ull, a03 = 0ull;
        unsigned long long a10 = 0ull, a11 = 0ull, a12 = 0ull, a13 = 0ull;
        const float* pT = sT + 4 * tx;
        const float* pE = sE + 4 * ty;
#pragma unroll 8
        for (int k = 0; k < 64; k++) {
            float4 tf = *reinterpret_cast<const float4*>(pT + k * LDE);
            ulonglong2 ef = *reinterpret_cast<const ulonglong2*>(pE + k * LDE);
            unsigned long long t0 = pk2(tf.x, tf.x);
            unsigned long long t1 = pk2(tf.y, tf.y);
            unsigned long long t2 = pk2(tf.z, tf.z);
            unsigned long long t3 = pk2(tf.w, tf.w);
            fma2(a00, ef.x, t0); fma2(a10, ef.y, t0);
            fma2(a01, ef.x, t1); fma2(a11, ef.y, t1);
            fma2(a02, ef.x, t2); fma2(a12, ef.y, t2);
            fma2(a03, ef.x, t3); fma2(a13, ef.y, t3);
        }

        // Epilogue: log, mask-weight, reduce over pairs.
        float2 u0, u1;
        u0 = up2(a00); u1 = up2(a10);
        float r0 = w0 * __logf(u0.x) + w1 * __logf(u0.y) + w2 * __logf(u1.x) + w3 * __logf(u1.y);
        u0 = up2(a01); u1 = up2(a11);
        float r1 = w0 * __logf(u0.x) + w1 * __logf(u0.y) + w2 * __logf(u1.x) + w3 * __logf(u1.y);
        u0 = up2(a02); u1 = up2(a12);
        float r2 = w0 * __logf(u0.x) + w1 * __logf(u0.y) + w2 * __logf(u1.x) + w3 * __logf(u1.y);
        u0 = up2(a03); u1 = up2(a13);
        float r3 = w0 * __logf(u0.x) + w1 * __logf(u0.y) + w2 * __logf(u1.x) + w3 * __logf(u1.y);

        sRed[(4 * tx + 0) * 17 + ty] = r0;
        sRed[(4 * tx + 1) * 17 + ty] = r1;
        sRed[(4 * tx + 2) * 17 + ty] = r2;
        sRed[(4 * tx + 3) * 17 + ty] = r3;
        __syncthreads();   // sRed ready; also all sE reads of this tile done

        if (tid < 64) {
            float s = 0.0f;
#pragma unroll
            for (int y2 = 0; y2 < 16; y2++) s += sRed[tid * 17 + y2];
            accA += s;
        }
        // Safe: next sRed writes happen only after the next sE-fill barrier.
    }

    if (tid < 64) atomicAdd(&g_alpha[tid], accA);
    __syncthreads();   // sRed reads done before phase-2 reuse

    // ---- Phase 2: score partial for (batch b, quarter q), g = blockIdx ----
    {
        const int g = blockIdx.x;
        const int b = g >> 2, q = g & 3;
        float acc = 0.0f; int cnt = 0;
        if (tid < 128) {
            const int s = q * 128 + tid;
            int lab = labels[b * SB + s];
            int mm  = mask[b * SB + s];
            if (mm != 0) {
                float v = emit[(b * SB + s) * LL + lab];
                if (s > 0) v += trans[labels[b * SB + s - 1] * LL + lab];
                acc = v; cnt = 1;
            }
        }
        float* rA = sRed;                       // 128 floats
        int*   rC = (int*)(sRed + 128);         // 128 ints
        if (tid < 128) { rA[tid] = acc; rC[tid] = cnt; }
        __syncthreads();
#pragma unroll
        for (int o = 64; o > 0; o >>= 1) {
            if (tid < o) { rA[tid] += rA[tid + o]; rC[tid] += rC[tid + o]; }
            __syncthreads();
        }
        if (tid == 0) {
            atomicAdd(&g_cntB[b], rC[0]);
            float add = rA[0];
            if (q == 0) add += strans[labels[b * SB]];
            atomicAdd(&g_score, add);
        }
    }
}

// ============================================================================
// Kernel B: single block, 128 threads — latency-minimal finish.
//   alpha_i = emit[0,0,i] + g_alpha[i]; logZ = LSE(alpha);
//   score = g_score + sum_b etrans[labels[b, g_cntB[b]-1]];
//   out = (logZ - score)/B.  Then reset accumulators for next graph replay.
// Dependent global chains: (g_cntB -> labels -> etrans) and (g_alpha), both
// issued up-front and overlapped.
// ============================================================================
__global__ void __launch_bounds__(128)
k_B(const float* __restrict__ emit,
    const int*   __restrict__ labels,
    const float* __restrict__ etrans,
    float* __restrict__ out) {
    __shared__ double sM[64];
    __shared__ double sSc[128];

    const int tid = threadIdx.x;

    // Kick off both dependent chains immediately.
    float gsc = (tid == 0) ? g_score : 0.0f;     // 1 load
    int   c   = g_cntB[tid];                     // chain A: cnt
    double a  = 0.0;
    if (tid < 64) a = (double)emit[tid] + (double)g_alpha[tid];  // chain B

    int   lab = labels[tid * SB + (c > 0 ? c - 1 : 0)];          // chain A: label
    double ev = (double)etrans[lab];                              // chain A: etrans

    // LSE over 64 alpha lanes.
    if (tid < 64) sM[tid] = a;
    __syncthreads();
#pragma unroll
    for (int o = 32; o > 0; o >>= 1) {
        if (tid < o) sM[tid] = fmax(sM[tid], sM[tid + o]);
        __syncthreads();
    }
    const double mx = sM[0];
    __syncthreads();
    if (tid < 64) sM[tid] = exp(a - mx);
    __syncthreads();
#pragma unroll
    for (int o = 32; o > 0; o >>= 1) {
        if (tid < o) sM[tid] += sM[tid + o];
        __syncthreads();
    }
    const double sumE = sM[0];

    // Sum etrans over 128 batches.
    sSc[tid] = ev;
    __syncthreads();
#pragma unroll
    for (int o = 64; o > 0; o >>= 1) {
        if (tid < o) sSc[tid] += sSc[tid + o];
        __syncthreads();
    }

    if (tid == 0) {
        double logZ = mx + log(sumE);
        double score = (double)gsc + sSc[0];
        out[0] = (float)((logZ - score) / (double)BB);
    }

    // Reset accumulators for the next graph replay (stream-ordered before
    // the next k_A; module load zero-initializes the first run).
    __syncthreads();
    if (tid < 64) g_alpha[tid] = 0.0f;
    g_cntB[tid] = 0;
    if (tid == 0) g_score = 0.0f;
}

// ============================================================================
// kernel_launch — two kernels (stream-ordered; graph-capturable).
// Inputs: emit f32[B,S,L], labels i32[B,S], mask i32[B,S] (bool as int32),
//         transitions f32[L,L], strans f32[L], etrans f32[L]. Output f32[1].
// ============================================================================
extern "C" void kernel_launch(void* const* d_in, const int* in_sizes, int n_in,
                              void* d_out, int out_size) {
    const float* emit   = (const float*)d_in[0];
    const int*   labels = (const int*)d_in[1];
    const int*   mask   = (const int*)d_in[2];
    const float* trans  = (const float*)d_in[3];
    const float* strans = (const float*)d_in[4];
    const float* etrans = (const float*)d_in[5];
    float* out = (float*)d_out;

    k_A<<<GRID_MAIN, 256>>>(emit, labels, mask, trans, strans);
    k_B<<<1, 128>>>(emit, labels, etrans, out);
}